// round 14
// baseline (speedup 1.0000x reference)
#include <cuda_runtime.h>
#include <cuda_bf16.h>
#include <cstdint>

#define N_NODES  50000
#define N_EDGES  800000
#define N_GRAPHS 512
#define IN_DIM   128
#define HID      64

#define SCAN_BLK 1024
#define N_SCAN_BLOCKS ((N_NODES + SCAN_BLK - 1) / SCAN_BLK)   // 49

// ---------------- device scratch (static, no allocation) ----------------
// ping-pong layer buffers: self (fp32) + msg (bf16x2)
__device__ float        g_selfA[(size_t)N_NODES * 64];
__device__ float        g_selfB[(size_t)N_NODES * 64];
__device__ unsigned int g_msgA[(size_t)N_NODES * 32];
__device__ unsigned int g_msgB[(size_t)N_NODES * 32];
__device__ float        g_h[(size_t)N_NODES * HID];     // layer-3 output (for pool)
__device__ int   g_deg[N_NODES];
__device__ int   g_ex[N_NODES];
__device__ int   g_off[N_NODES + 1];           // CSR offsets (by dst)
__device__ int   g_pos[N_NODES];
__device__ int   g_srcs[N_EDGES];              // CSR column (src node)
__device__ int   g_bsum[N_SCAN_BLOCKS];
__device__ int   g_gstart[N_GRAPHS + 1];
__device__ int   g_is64;                       // 1 if index tensors are int64

// ---------------- helpers ----------------
__device__ __forceinline__ int load_idx(const void* p, long long i, int is64) {
    if (is64) return (int)((const long long*)p)[i];
    return ((const int*)p)[i];
}
__device__ __forceinline__ int clampi(int v, int lo, int hi) {
    return v < lo ? lo : (v > hi ? hi : v);
}
__device__ __forceinline__ unsigned long long ffma2(unsigned long long a,
                                                    unsigned long long b,
                                                    unsigned long long c) {
    unsigned long long d;
    asm("fma.rn.f32x2 %0, %1, %2, %3;" : "=l"(d) : "l"(a), "l"(b), "l"(c));
    return d;
}
__device__ __forceinline__ unsigned long long dup2(float v) {
    unsigned long long r;
    unsigned u = __float_as_uint(v);
    asm("mov.b64 %0, {%1, %1};" : "=l"(r) : "r"(u));
    return r;
}
__device__ __forceinline__ unsigned int pack_bf16x2(float lo, float hi) {
    unsigned int r;
    asm("cvt.rn.bf16x2.f32 %0, %1, %2;" : "=r"(r) : "f"(hi), "f"(lo));
    return r;
}

// ---------------- zero + dtype detect (fused) ----------------
__global__ void zero_detect_kernel(const void* ei) {
    int i = blockIdx.x * blockDim.x + threadIdx.x;
    if (i < N_NODES) g_deg[i] = 0;
    if (blockIdx.x == 0) {
        if (threadIdx.x == 0) g_is64 = 1;
        __syncthreads();
        // int64 data (<2^31) has all-zero odd 32-bit words; int32 ids do not.
        const int* p = (const int*)ei;
        int nz = 0;
        for (int q = threadIdx.x; q < 4096; q += blockDim.x)
            if (p[2 * q + 1] != 0) nz = 1;
        if (nz) atomicExch(&g_is64, 0);
    }
}

__global__ void hist_kernel(const void* __restrict__ edge_index) {
    int e = blockIdx.x * blockDim.x + threadIdx.x;
    if (e < N_EDGES) {
        int is64 = g_is64;
        int d = clampi(load_idx(edge_index, (long long)N_EDGES + e, is64), 0, N_NODES - 1);
        atomicAdd(&g_deg[d], 1);
    }
}

// shuffle-based block scan (2 barriers)
__global__ void scan_block_kernel() {
    __shared__ int wsum[32];
    int i = blockIdx.x * SCAN_BLK + threadIdx.x;
    int v = (i < N_NODES) ? g_deg[i] : 0;
    int lane = threadIdx.x & 31;
    int wid  = threadIdx.x >> 5;
    int x = v;
    #pragma unroll
    for (int d = 1; d < 32; d <<= 1) {
        int y = __shfl_up_sync(0xFFFFFFFFu, x, d);
        if (lane >= d) x += y;
    }
    if (lane == 31) wsum[wid] = x;
    __syncthreads();
    if (wid == 0) {
        int s = wsum[lane];
        #pragma unroll
        for (int d = 1; d < 32; d <<= 1) {
            int y = __shfl_up_sync(0xFFFFFFFFu, s, d);
            if (lane >= d) s += y;
        }
        wsum[lane] = s;
    }
    __syncthreads();
    int incl = x + (wid > 0 ? wsum[wid - 1] : 0);
    if (i < N_NODES) g_ex[i] = incl - v;
    if (threadIdx.x == SCAN_BLK - 1) g_bsum[blockIdx.x] = incl;
}

// scan finalize: every block redundantly scans the 49 block sums (cheap),
// then writes offsets/cursors and graph starts.
__global__ void scan_fin_kernel(const void* __restrict__ batch) {
    __shared__ int pre[64];
    int tid = threadIdx.x;
    if (tid < 64) {
        int v = (tid < N_SCAN_BLOCKS) ? g_bsum[tid] : 0;
        int lane = tid & 31;
        int x = v;
        #pragma unroll
        for (int d = 1; d < 32; d <<= 1) {
            int y = __shfl_up_sync(0xFFFFFFFFu, x, d);
            if (lane >= d) x += y;
        }
        pre[tid] = x;
    }
    __syncthreads();
    if (tid >= 32 && tid < 64) pre[tid] += pre[31];
    __syncthreads();
    int bpre = (blockIdx.x == 0) ? 0 : pre[blockIdx.x - 1];

    int i = blockIdx.x * SCAN_BLK + tid;
    if (i < N_NODES) {
        int v = g_ex[i] + bpre;
        g_off[i] = v;
        g_pos[i] = v;
        int is64 = g_is64;
        int b = clampi(load_idx(batch, i, is64), 0, N_GRAPHS - 1);
        if (i == 0) {
            for (int g = 0; g <= b; g++) g_gstart[g] = 0;
        } else {
            int bp = clampi(load_idx(batch, i - 1, is64), 0, N_GRAPHS - 1);
            for (int g = bp + 1; g <= b; g++) g_gstart[g] = i;
        }
        if (i == N_NODES - 1) {
            for (int g = b + 1; g <= N_GRAPHS; g++) g_gstart[g] = N_NODES;
        }
    }
    if (i == 0) g_off[N_NODES] = N_EDGES;
}

__global__ void fill_kernel(const void* __restrict__ edge_index) {
    int e = blockIdx.x * blockDim.x + threadIdx.x;
    if (e < N_EDGES) {
        int is64 = g_is64;
        int s = clampi(load_idx(edge_index, e, is64), 0, N_NODES - 1);
        int d = clampi(load_idx(edge_index, (long long)N_EDGES + e, is64), 0, N_NODES - 1);
        int idx = atomicAdd(&g_pos[d], 1);
        if (idx >= 0 && idx < N_EDGES) g_srcs[idx] = s;
    }
}

// ---------------- shared epilogue: write [self fp32 | msg bf16] ----------------
__device__ __forceinline__ void gemm_epilogue(unsigned long long acc[4][8],
                                              int row0, int tx, int ty,
                                              float* sout, unsigned int* mout) {
    #pragma unroll
    for (int rp = 0; rp < 4; rp++) {
        int r = row0 + ty * 8 + rp * 2;
        float lo[8], hi[8];
        #pragma unroll
        for (int j = 0; j < 8; j++) {
            lo[j] = __uint_as_float((unsigned)acc[rp][j]);
            hi[j] = __uint_as_float((unsigned)(acc[rp][j] >> 32));
        }
        if (tx < 8) {
            if (r < N_NODES) {
                *(float4*)&sout[(size_t)r * 64 + tx * 8]     = make_float4(lo[0], lo[1], lo[2], lo[3]);
                *(float4*)&sout[(size_t)r * 64 + tx * 8 + 4] = make_float4(lo[4], lo[5], lo[6], lo[7]);
            }
            if (r + 1 < N_NODES) {
                *(float4*)&sout[(size_t)(r + 1) * 64 + tx * 8]     = make_float4(hi[0], hi[1], hi[2], hi[3]);
                *(float4*)&sout[(size_t)(r + 1) * 64 + tx * 8 + 4] = make_float4(hi[4], hi[5], hi[6], hi[7]);
            }
        } else {
            int c0 = (tx - 8) * 4;
            if (r < N_NODES) {
                uint4 v = make_uint4(pack_bf16x2(lo[0], lo[1]), pack_bf16x2(lo[2], lo[3]),
                                     pack_bf16x2(lo[4], lo[5]), pack_bf16x2(lo[6], lo[7]));
                *(uint4*)&mout[(size_t)r * 32 + c0] = v;
            }
            if (r + 1 < N_NODES) {
                uint4 v = make_uint4(pack_bf16x2(hi[0], hi[1]), pack_bf16x2(hi[2], hi[3]),
                                     pack_bf16x2(hi[4], hi[5]), pack_bf16x2(hi[6], hi[7]));
                *(uint4*)&mout[(size_t)(r + 1) * 32 + c0] = v;
            }
        }
    }
}

// ---------------- layer-1 GEMM: bufA = x[N,128] @ [W1 | W2] ----------------
__global__ __launch_bounds__(128)
void gemm1_kernel(const float* __restrict__ F,
                  const float* __restrict__ W1,
                  const float* __restrict__ W2) {
    __shared__ __align__(16) float As[16][64];
    __shared__ __align__(16) float Bs[16][128];

    const int tid  = threadIdx.x;
    const int row0 = blockIdx.x * 64;
    const int tx   = tid & 15;
    const int ty   = tid >> 4;

    unsigned long long acc[4][8];
    #pragma unroll
    for (int i = 0; i < 4; i++)
        #pragma unroll
        for (int j = 0; j < 8; j++) acc[i][j] = 0ull;

    for (int k0 = 0; k0 < IN_DIM; k0 += 16) {
        #pragma unroll
        for (int q = tid; q < 256; q += 128) {
            int r  = q >> 2;
            int kk = (q & 3) * 4;
            float4 v = make_float4(0.f, 0.f, 0.f, 0.f);
            int gr = row0 + r;
            if (gr < N_NODES) v = *(const float4*)&F[(size_t)gr * IN_DIM + k0 + kk];
            As[kk + 0][r] = v.x; As[kk + 1][r] = v.y;
            As[kk + 2][r] = v.z; As[kk + 3][r] = v.w;
        }
        #pragma unroll
        for (int q = tid; q < 512; q += 128) {
            int kr = q >> 5;
            int c4 = (q & 31) * 4;
            const float* Wp = (c4 < 64) ? &W1[(size_t)(k0 + kr) * 64 + c4]
                                        : &W2[(size_t)(k0 + kr) * 64 + (c4 - 64)];
            *(float4*)&Bs[kr][c4] = *(const float4*)Wp;
        }
        __syncthreads();

        #pragma unroll
        for (int k = 0; k < 16; k++) {
            const ulonglong2* ap = (const ulonglong2*)&As[k][ty * 8];
            ulonglong2 a01 = ap[0], a23 = ap[1];
            unsigned long long a[4] = {a01.x, a01.y, a23.x, a23.y};
            const float4* bp = (const float4*)&Bs[k][tx * 8];
            float4 b0 = bp[0], b1 = bp[1];
            unsigned long long b[8] = {dup2(b0.x), dup2(b0.y), dup2(b0.z), dup2(b0.w),
                                       dup2(b1.x), dup2(b1.y), dup2(b1.z), dup2(b1.w)};
            #pragma unroll
            for (int rp = 0; rp < 4; rp++)
                #pragma unroll
                for (int j = 0; j < 8; j++)
                    acc[rp][j] = ffma2(a[rp], b[j], acc[rp][j]);
        }
        __syncthreads();
    }
    gemm_epilogue(acc, row0, tx, ty, g_selfA, g_msgA);
}

// ------- fused gather(+ReLU) + GEMM for layers 2/3 (K = HID = 64) -------
// IN_A: read self/msg from buffer A, write to B; else B -> A.
// Phase 1: each of 4 warps gathers 16 of the block's 64 rows into Ah[k][row].
// Phase 2: standard f32x2 GEMM with A from smem.
// Row stride 68 floats = 272 B = 17*16 -> every Ah[k][ty*8] is 16B-aligned
// (stride MUST be a multiple of 16B for the LDS.128 in the mainloop).
template <bool IN_A>
__global__ __launch_bounds__(128)
void fused_gather_gemm_kernel(const float* __restrict__ W1,
                              const float* __restrict__ W2) {
    __shared__ __align__(16) float Ah[64][68];
    __shared__ __align__(16) float Bs[16][128];

    const float*        self_in = IN_A ? g_selfA : g_selfB;
    const unsigned int* msg_in  = IN_A ? g_msgA  : g_msgB;
    float*              self_out = IN_A ? g_selfB : g_selfA;
    unsigned int*       msg_out  = IN_A ? g_msgB  : g_msgA;

    const int tid  = threadIdx.x;
    const int row0 = blockIdx.x * 64;
    const int wid  = tid >> 5;
    const int lane = tid & 31;

    // Phase 1: gather + ReLU into Ah (transposed)
    #pragma unroll 1
    for (int n = 0; n < 16; n++) {
        int r = wid * 16 + n;          // local row
        int node = row0 + r;
        float ax = 0.f, ay = 0.f;
        if (node < N_NODES) {
            int s = g_off[node], e = g_off[node + 1];
            int i = s;
            for (; i + 3 < e; i += 4) {
                int u0 = g_srcs[i], u1 = g_srcs[i + 1], u2 = g_srcs[i + 2], u3 = g_srcs[i + 3];
                unsigned p0 = msg_in[(size_t)u0 * 32 + lane];
                unsigned p1 = msg_in[(size_t)u1 * 32 + lane];
                unsigned p2 = msg_in[(size_t)u2 * 32 + lane];
                unsigned p3 = msg_in[(size_t)u3 * 32 + lane];
                ax += __uint_as_float(p0 << 16) + __uint_as_float(p1 << 16)
                    + __uint_as_float(p2 << 16) + __uint_as_float(p3 << 16);
                ay += __uint_as_float(p0 & 0xFFFF0000u) + __uint_as_float(p1 & 0xFFFF0000u)
                    + __uint_as_float(p2 & 0xFFFF0000u) + __uint_as_float(p3 & 0xFFFF0000u);
            }
            for (; i < e; i++) {
                unsigned p = msg_in[(size_t)g_srcs[i] * 32 + lane];
                ax += __uint_as_float(p << 16);
                ay += __uint_as_float(p & 0xFFFF0000u);
            }
            float2 self = *(const float2*)(self_in + (size_t)node * 64 + 2 * lane);
            ax = fmaxf(self.x + ax, 0.f);
            ay = fmaxf(self.y + ay, 0.f);
        }
        Ah[2 * lane][r]     = ax;
        Ah[2 * lane + 1][r] = ay;
    }
    __syncthreads();

    // Phase 2: GEMM (K = 64)
    const int tx = tid & 15;
    const int ty = tid >> 4;
    unsigned long long acc[4][8];
    #pragma unroll
    for (int i = 0; i < 4; i++)
        #pragma unroll
        for (int j = 0; j < 8; j++) acc[i][j] = 0ull;

    for (int k0 = 0; k0 < HID; k0 += 16) {
        #pragma unroll
        for (int q = tid; q < 512; q += 128) {
            int kr = q >> 5;
            int c4 = (q & 31) * 4;
            const float* Wp = (c4 < 64) ? &W1[(size_t)(k0 + kr) * 64 + c4]
                                        : &W2[(size_t)(k0 + kr) * 64 + (c4 - 64)];
            *(float4*)&Bs[kr][c4] = *(const float4*)Wp;
        }
        __syncthreads();

        #pragma unroll
        for (int k = 0; k < 16; k++) {
            const ulonglong2* ap = (const ulonglong2*)&Ah[k0 + k][ty * 8];
            ulonglong2 a01 = ap[0], a23 = ap[1];
            unsigned long long a[4] = {a01.x, a01.y, a23.x, a23.y};
            const float4* bp = (const float4*)&Bs[k][tx * 8];
            float4 b0 = bp[0], b1 = bp[1];
            unsigned long long b[8] = {dup2(b0.x), dup2(b0.y), dup2(b0.z), dup2(b0.w),
                                       dup2(b1.x), dup2(b1.y), dup2(b1.z), dup2(b1.w)};
            #pragma unroll
            for (int rp = 0; rp < 4; rp++)
                #pragma unroll
                for (int j = 0; j < 8; j++)
                    acc[rp][j] = ffma2(a[rp], b[j], acc[rp][j]);
        }
        __syncthreads();
    }
    gemm_epilogue(acc, row0, tx, ty, self_out, msg_out);
}

// ---------------- layer-3 gather: bufA -> g_h (warp per node) ----------------
__global__ __launch_bounds__(256)
void gather_relu_kernel() {
    int w    = (blockIdx.x * blockDim.x + threadIdx.x) >> 5;
    int lane = threadIdx.x & 31;
    if (w >= N_NODES) return;
    int s = g_off[w], e = g_off[w + 1];
    float ax = 0.f, ay = 0.f;
    int i = s;
    for (; i + 3 < e; i += 4) {
        int u0 = g_srcs[i], u1 = g_srcs[i + 1], u2 = g_srcs[i + 2], u3 = g_srcs[i + 3];
        unsigned p0 = g_msgA[(size_t)u0 * 32 + lane];
        unsigned p1 = g_msgA[(size_t)u1 * 32 + lane];
        unsigned p2 = g_msgA[(size_t)u2 * 32 + lane];
        unsigned p3 = g_msgA[(size_t)u3 * 32 + lane];
        ax += __uint_as_float(p0 << 16) + __uint_as_float(p1 << 16)
            + __uint_as_float(p2 << 16) + __uint_as_float(p3 << 16);
        ay += __uint_as_float(p0 & 0xFFFF0000u) + __uint_as_float(p1 & 0xFFFF0000u)
            + __uint_as_float(p2 & 0xFFFF0000u) + __uint_as_float(p3 & 0xFFFF0000u);
    }
    for (; i < e; i++) {
        unsigned p = g_msgA[(size_t)g_srcs[i] * 32 + lane];
        ax += __uint_as_float(p << 16);
        ay += __uint_as_float(p & 0xFFFF0000u);
    }
    float2 self = *(const float2*)(g_selfA + (size_t)w * 64 + 2 * lane);
    float2 o;
    o.x = fmaxf(self.x + ax, 0.f);
    o.y = fmaxf(self.y + ay, 0.f);
    *(float2*)(g_h + (size_t)w * HID + 2 * lane) = o;
}

// ---------------- fused mean-pool + classifier (block per graph) ----------------
__global__ __launch_bounds__(64)
void pool_classify_kernel(const float* __restrict__ cW1, const float* __restrict__ cb1,
                          const float* __restrict__ cW2, const float* __restrict__ cb2,
                          float* __restrict__ out) {
    int g = blockIdx.x;
    int t = threadIdx.x;  // 64
    int s = g_gstart[g], e = g_gstart[g + 1];
    float sum = 0.f;
    for (int n = s; n < e; n++) sum += g_h[(size_t)n * HID + t];
    float cnt = (float)(e - s);
    __shared__ float mean[HID];
    mean[t] = sum / fmaxf(cnt, 1.f);
    __syncthreads();
    float acc = cb1[t];
    #pragma unroll
    for (int k = 0; k < HID; k++) acc = fmaf(mean[k], cW1[k * HID + t], acc);
    float v = fmaxf(acc, 0.f) * cW2[t];
    __shared__ float red[HID];
    red[t] = v;
    __syncthreads();
    if (t < 32) {
        float x = red[t] + red[t + 32];
        #pragma unroll
        for (int ofs = 16; ofs >= 1; ofs >>= 1)
            x += __shfl_down_sync(0xFFFFFFFFu, x, ofs);
        if (t == 0) out[g] = x + cb2[0];
    }
}

// ---------------- launch ----------------
extern "C" void kernel_launch(void* const* d_in, const int* in_sizes, int n_in,
                              void* d_out, int out_size) {
    const float* x     = (const float*)d_in[0];
    const void*  ei    = d_in[1];
    const void*  batch = d_in[2];
    const float* W1_1 = (const float*)d_in[3];
    const float* W2_1 = (const float*)d_in[4];
    const float* W1_2 = (const float*)d_in[5];
    const float* W2_2 = (const float*)d_in[6];
    const float* W1_3 = (const float*)d_in[7];
    const float* W2_3 = (const float*)d_in[8];
    const float* cW1  = (const float*)d_in[9];
    const float* cb1  = (const float*)d_in[10];
    const float* cW2  = (const float*)d_in[11];
    const float* cb2  = (const float*)d_in[12];
    float* out = (float*)d_out;

    const int EB = (N_EDGES + 255) / 256;
    const int NB = (N_NODES + 255) / 256;
    const int GEMM_BLOCKS = (N_NODES + 63) / 64;
    const int GATHER_BLOCKS = (N_NODES * 32 + 255) / 256;

    // Side stream: GEMM layer 1 (depends only on x/weights) overlaps the CSR build.
    cudaStream_t sB;
    cudaStreamCreateWithFlags(&sB, cudaStreamNonBlocking);
    cudaEvent_t evFork, evGemm;
    cudaEventCreateWithFlags(&evFork, cudaEventDisableTiming);
    cudaEventCreateWithFlags(&evGemm, cudaEventDisableTiming);

    cudaEventRecord(evFork, 0);
    cudaStreamWaitEvent(sB, evFork, 0);
    gemm1_kernel<<<GEMM_BLOCKS, 128, 0, sB>>>(x, W1_1, W2_1);
    cudaEventRecord(evGemm, sB);

    // CSR build on the main stream (concurrent with GEMM L1)
    zero_detect_kernel<<<NB, 256>>>(ei);
    hist_kernel<<<EB, 256>>>(ei);
    scan_block_kernel<<<N_SCAN_BLOCKS, SCAN_BLK>>>();
    scan_fin_kernel<<<N_SCAN_BLOCKS, SCAN_BLK>>>(batch);
    fill_kernel<<<EB, 256>>>(ei);

    // Join: fused layer 2 needs CSR + GEMM L1 output
    cudaStreamWaitEvent(0, evGemm, 0);
    fused_gather_gemm_kernel<true><<<GEMM_BLOCKS, 128>>>(W1_2, W2_2);   // A -> B
    fused_gather_gemm_kernel<false><<<GEMM_BLOCKS, 128>>>(W1_3, W2_3);  // B -> A
    gather_relu_kernel<<<GATHER_BLOCKS, 256>>>();                       // A -> g_h
    pool_classify_kernel<<<N_GRAPHS, HID>>>(cW1, cb1, cW2, cb2, out);
}

// round 15
// speedup vs baseline: 1.5207x; 1.5207x over previous
#include <cuda_runtime.h>
#include <cuda_bf16.h>
#include <cstdint>

#define N_NODES  50000
#define N_EDGES  800000
#define N_GRAPHS 512
#define IN_DIM   128
#define HID      64

#define SCAN_BLK 1024
#define N_SCAN_BLOCKS ((N_NODES + SCAN_BLK - 1) / SCAN_BLK)   // 49

// ---------------- device scratch (static, no allocation) ----------------
__device__ float        g_self[(size_t)N_NODES * 64];   // GEMM self part (fp32)
__device__ unsigned int g_msg[(size_t)N_NODES * 32];    // GEMM msg part (bf16x2)
__device__ float        g_h[(size_t)N_NODES * HID];     // layer output features
__device__ int   g_deg[N_NODES];
__device__ int   g_ex[N_NODES];
__device__ int   g_off[N_NODES + 1];           // CSR offsets (by dst)
__device__ int   g_pos[N_NODES];
__device__ int   g_srcs[N_EDGES];              // CSR column (src node)
__device__ int   g_bsum[N_SCAN_BLOCKS];
__device__ int   g_gstart[N_GRAPHS + 1];
__device__ int   g_is64;                       // 1 if index tensors are int64

// ---------------- helpers ----------------
__device__ __forceinline__ int load_idx(const void* p, long long i, int is64) {
    if (is64) return (int)((const long long*)p)[i];
    return ((const int*)p)[i];
}
__device__ __forceinline__ int clampi(int v, int lo, int hi) {
    return v < lo ? lo : (v > hi ? hi : v);
}
__device__ __forceinline__ unsigned long long ffma2(unsigned long long a,
                                                    unsigned long long b,
                                                    unsigned long long c) {
    unsigned long long d;
    asm("fma.rn.f32x2 %0, %1, %2, %3;" : "=l"(d) : "l"(a), "l"(b), "l"(c));
    return d;
}
__device__ __forceinline__ unsigned long long dup2(float v) {
    unsigned long long r;
    unsigned u = __float_as_uint(v);
    asm("mov.b64 %0, {%1, %1};" : "=l"(r) : "r"(u));
    return r;
}
__device__ __forceinline__ unsigned int pack_bf16x2(float lo, float hi) {
    unsigned int r;
    asm("cvt.rn.bf16x2.f32 %0, %1, %2;" : "=r"(r) : "f"(hi), "f"(lo));
    return r;
}

// ---------------- zero + dtype detect (fused) ----------------
__global__ void zero_detect_kernel(const void* ei) {
    int i = blockIdx.x * blockDim.x + threadIdx.x;
    if (i < N_NODES) g_deg[i] = 0;
    if (blockIdx.x == 0) {
        if (threadIdx.x == 0) g_is64 = 1;
        __syncthreads();
        // int64 data (<2^31) has all-zero odd 32-bit words; int32 ids do not.
        const int* p = (const int*)ei;
        int nz = 0;
        for (int q = threadIdx.x; q < 4096; q += blockDim.x)
            if (p[2 * q + 1] != 0) nz = 1;
        if (nz) atomicExch(&g_is64, 0);
    }
}

// 4 edges per thread: 4 independent atomics in flight
__global__ void hist_kernel(const void* __restrict__ edge_index) {
    int e0 = (blockIdx.x * blockDim.x + threadIdx.x) * 4;
    int is64 = g_is64;
    #pragma unroll
    for (int q = 0; q < 4; q++) {
        int e = e0 + q;
        if (e < N_EDGES) {
            int d = clampi(load_idx(edge_index, (long long)N_EDGES + e, is64), 0, N_NODES - 1);
            atomicAdd(&g_deg[d], 1);
        }
    }
}

// shuffle-based block scan (2 barriers)
__global__ void scan_block_kernel() {
    __shared__ int wsum[32];
    int i = blockIdx.x * SCAN_BLK + threadIdx.x;
    int v = (i < N_NODES) ? g_deg[i] : 0;
    int lane = threadIdx.x & 31;
    int wid  = threadIdx.x >> 5;
    int x = v;
    #pragma unroll
    for (int d = 1; d < 32; d <<= 1) {
        int y = __shfl_up_sync(0xFFFFFFFFu, x, d);
        if (lane >= d) x += y;
    }
    if (lane == 31) wsum[wid] = x;
    __syncthreads();
    if (wid == 0) {
        int s = wsum[lane];
        #pragma unroll
        for (int d = 1; d < 32; d <<= 1) {
            int y = __shfl_up_sync(0xFFFFFFFFu, s, d);
            if (lane >= d) s += y;
        }
        wsum[lane] = s;
    }
    __syncthreads();
    int incl = x + (wid > 0 ? wsum[wid - 1] : 0);
    if (i < N_NODES) g_ex[i] = incl - v;
    if (threadIdx.x == SCAN_BLK - 1) g_bsum[blockIdx.x] = incl;
}

// scan finalize: every block redundantly scans the 49 block sums (cheap),
// then writes offsets/cursors and graph starts.
__global__ void scan_fin_kernel(const void* __restrict__ batch) {
    __shared__ int pre[64];
    int tid = threadIdx.x;
    if (tid < 64) {
        int v = (tid < N_SCAN_BLOCKS) ? g_bsum[tid] : 0;
        int lane = tid & 31;
        int x = v;
        #pragma unroll
        for (int d = 1; d < 32; d <<= 1) {
            int y = __shfl_up_sync(0xFFFFFFFFu, x, d);
            if (lane >= d) x += y;
        }
        pre[tid] = x;
    }
    __syncthreads();
    if (tid >= 32 && tid < 64) pre[tid] += pre[31];
    __syncthreads();
    int bpre = (blockIdx.x == 0) ? 0 : pre[blockIdx.x - 1];

    int i = blockIdx.x * SCAN_BLK + tid;
    if (i < N_NODES) {
        int v = g_ex[i] + bpre;
        g_off[i] = v;
        g_pos[i] = v;
        int is64 = g_is64;
        int b = clampi(load_idx(batch, i, is64), 0, N_GRAPHS - 1);
        if (i == 0) {
            for (int g = 0; g <= b; g++) g_gstart[g] = 0;
        } else {
            int bp = clampi(load_idx(batch, i - 1, is64), 0, N_GRAPHS - 1);
            for (int g = bp + 1; g <= b; g++) g_gstart[g] = i;
        }
        if (i == N_NODES - 1) {
            for (int g = b + 1; g <= N_GRAPHS; g++) g_gstart[g] = N_NODES;
        }
    }
    if (i == 0) g_off[N_NODES] = N_EDGES;
}

// 4 edges per thread: 4 independent returning atomics pipelined
__global__ void fill_kernel(const void* __restrict__ edge_index) {
    int e0 = (blockIdx.x * blockDim.x + threadIdx.x) * 4;
    int is64 = g_is64;
    int s[4], d[4], idx[4];
    #pragma unroll
    for (int q = 0; q < 4; q++) {
        int e = e0 + q;
        if (e < N_EDGES) {
            s[q] = clampi(load_idx(edge_index, e, is64), 0, N_NODES - 1);
            d[q] = clampi(load_idx(edge_index, (long long)N_EDGES + e, is64), 0, N_NODES - 1);
        }
    }
    #pragma unroll
    for (int q = 0; q < 4; q++) {
        int e = e0 + q;
        if (e < N_EDGES) idx[q] = atomicAdd(&g_pos[d[q]], 1);
    }
    #pragma unroll
    for (int q = 0; q < 4; q++) {
        int e = e0 + q;
        if (e < N_EDGES && idx[q] >= 0 && idx[q] < N_EDGES) g_srcs[idx[q]] = s[q];
    }
}

// ---------------- GEMM: [self fp32 | msg bf16] = F[N,K] @ [W1 | W2] ----------------
// Block: 64 rows x 128 cols, 128 threads, each thread 8 rows (4 f32x2 pairs) x 8 cols.
template <int K, bool FROM_GH>
__global__ __launch_bounds__(128)
void gemm_cat_kernel(const float* __restrict__ F,
                     const float* __restrict__ W1,
                     const float* __restrict__ W2) {
    __shared__ __align__(16) float As[16][64];
    __shared__ __align__(16) float Bs[16][128];

    const float* Fp = FROM_GH ? (const float*)g_h : F;

    const int tid  = threadIdx.x;
    const int row0 = blockIdx.x * 64;
    const int tx   = tid & 15;
    const int ty   = tid >> 4;

    unsigned long long acc[4][8];
    #pragma unroll
    for (int i = 0; i < 4; i++)
        #pragma unroll
        for (int j = 0; j < 8; j++) acc[i][j] = 0ull;

    for (int k0 = 0; k0 < K; k0 += 16) {
        #pragma unroll
        for (int q = tid; q < 256; q += 128) {
            int r  = q >> 2;
            int kk = (q & 3) * 4;
            float4 v = make_float4(0.f, 0.f, 0.f, 0.f);
            int gr = row0 + r;
            if (gr < N_NODES) v = *(const float4*)&Fp[(size_t)gr * K + k0 + kk];
            As[kk + 0][r] = v.x; As[kk + 1][r] = v.y;
            As[kk + 2][r] = v.z; As[kk + 3][r] = v.w;
        }
        #pragma unroll
        for (int q = tid; q < 512; q += 128) {
            int kr = q >> 5;
            int c4 = (q & 31) * 4;
            const float* Wp = (c4 < 64) ? &W1[(size_t)(k0 + kr) * 64 + c4]
                                        : &W2[(size_t)(k0 + kr) * 64 + (c4 - 64)];
            *(float4*)&Bs[kr][c4] = *(const float4*)Wp;
        }
        __syncthreads();

        #pragma unroll
        for (int k = 0; k < 16; k++) {
            const ulonglong2* ap = (const ulonglong2*)&As[k][ty * 8];
            ulonglong2 a01 = ap[0], a23 = ap[1];
            unsigned long long a[4] = {a01.x, a01.y, a23.x, a23.y};
            const float4* bp = (const float4*)&Bs[k][tx * 8];
            float4 b0 = bp[0], b1 = bp[1];
            unsigned long long b[8] = {dup2(b0.x), dup2(b0.y), dup2(b0.z), dup2(b0.w),
                                       dup2(b1.x), dup2(b1.y), dup2(b1.z), dup2(b1.w)};
            #pragma unroll
            for (int rp = 0; rp < 4; rp++)
                #pragma unroll
                for (int j = 0; j < 8; j++)
                    acc[rp][j] = ffma2(a[rp], b[j], acc[rp][j]);
        }
        __syncthreads();
    }

    // epilogue: self half fp32, msg half packed bf16x2
    #pragma unroll
    for (int rp = 0; rp < 4; rp++) {
        int r = row0 + ty * 8 + rp * 2;
        float lo[8], hi[8];
        #pragma unroll
        for (int j = 0; j < 8; j++) {
            lo[j] = __uint_as_float((unsigned)acc[rp][j]);
            hi[j] = __uint_as_float((unsigned)(acc[rp][j] >> 32));
        }
        if (tx < 8) {
            if (r < N_NODES) {
                *(float4*)&g_self[(size_t)r * 64 + tx * 8]     = make_float4(lo[0], lo[1], lo[2], lo[3]);
                *(float4*)&g_self[(size_t)r * 64 + tx * 8 + 4] = make_float4(lo[4], lo[5], lo[6], lo[7]);
            }
            if (r + 1 < N_NODES) {
                *(float4*)&g_self[(size_t)(r + 1) * 64 + tx * 8]     = make_float4(hi[0], hi[1], hi[2], hi[3]);
                *(float4*)&g_self[(size_t)(r + 1) * 64 + tx * 8 + 4] = make_float4(hi[4], hi[5], hi[6], hi[7]);
            }
        } else {
            int c0 = (tx - 8) * 4;
            if (r < N_NODES) {
                uint4 v = make_uint4(pack_bf16x2(lo[0], lo[1]), pack_bf16x2(lo[2], lo[3]),
                                     pack_bf16x2(lo[4], lo[5]), pack_bf16x2(lo[6], lo[7]));
                *(uint4*)&g_msg[(size_t)r * 32 + c0] = v;
            }
            if (r + 1 < N_NODES) {
                uint4 v = make_uint4(pack_bf16x2(hi[0], hi[1]), pack_bf16x2(hi[2], hi[3]),
                                     pack_bf16x2(hi[4], hi[5]), pack_bf16x2(hi[6], hi[7]));
                *(uint4*)&g_msg[(size_t)(r + 1) * 32 + c0] = v;
            }
        }
    }
}

// ---------------- neighbor gather + self + ReLU (warp per node, bf16 msgs) ----------------
__global__ __launch_bounds__(256)
void gather_relu_kernel() {
    int w    = (blockIdx.x * blockDim.x + threadIdx.x) >> 5;
    int lane = threadIdx.x & 31;
    if (w >= N_NODES) return;
    int s = g_off[w], e = g_off[w + 1];
    float ax = 0.f, ay = 0.f;
    int i = s;
    for (; i + 7 < e; i += 8) {
        unsigned p[8];
        #pragma unroll
        for (int q = 0; q < 8; q++) {
            int u = g_srcs[i + q];
            p[q] = g_msg[(size_t)u * 32 + lane];
        }
        #pragma unroll
        for (int q = 0; q < 8; q++) {
            ax += __uint_as_float(p[q] << 16);
            ay += __uint_as_float(p[q] & 0xFFFF0000u);
        }
    }
    for (; i + 3 < e; i += 4) {
        unsigned p[4];
        #pragma unroll
        for (int q = 0; q < 4; q++) {
            int u = g_srcs[i + q];
            p[q] = g_msg[(size_t)u * 32 + lane];
        }
        #pragma unroll
        for (int q = 0; q < 4; q++) {
            ax += __uint_as_float(p[q] << 16);
            ay += __uint_as_float(p[q] & 0xFFFF0000u);
        }
    }
    for (; i < e; i++) {
        unsigned p = g_msg[(size_t)g_srcs[i] * 32 + lane];
        ax += __uint_as_float(p << 16);
        ay += __uint_as_float(p & 0xFFFF0000u);
    }
    float2 self = *(const float2*)(g_self + (size_t)w * 64 + 2 * lane);
    float2 o;
    o.x = fmaxf(self.x + ax, 0.f);
    o.y = fmaxf(self.y + ay, 0.f);
    *(float2*)(g_h + (size_t)w * HID + 2 * lane) = o;
}

// ---------------- fused mean-pool + classifier (block per graph) ----------------
__global__ __launch_bounds__(64)
void pool_classify_kernel(const float* __restrict__ cW1, const float* __restrict__ cb1,
                          const float* __restrict__ cW2, const float* __restrict__ cb2,
                          float* __restrict__ out) {
    int g = blockIdx.x;
    int t = threadIdx.x;  // 64
    int s = g_gstart[g], e = g_gstart[g + 1];
    float sum = 0.f;
    for (int n = s; n < e; n++) sum += g_h[(size_t)n * HID + t];
    float cnt = (float)(e - s);
    __shared__ float mean[HID];
    mean[t] = sum / fmaxf(cnt, 1.f);
    __syncthreads();
    float acc = cb1[t];
    #pragma unroll
    for (int k = 0; k < HID; k++) acc = fmaf(mean[k], cW1[k * HID + t], acc);
    float v = fmaxf(acc, 0.f) * cW2[t];
    __shared__ float red[HID];
    red[t] = v;
    __syncthreads();
    if (t < 32) {
        float x = red[t] + red[t + 32];
        #pragma unroll
        for (int ofs = 16; ofs >= 1; ofs >>= 1)
            x += __shfl_down_sync(0xFFFFFFFFu, x, ofs);
        if (t == 0) out[g] = x + cb2[0];
    }
}

// ---------------- launch ----------------
extern "C" void kernel_launch(void* const* d_in, const int* in_sizes, int n_in,
                              void* d_out, int out_size) {
    const float* x     = (const float*)d_in[0];
    const void*  ei    = d_in[1];
    const void*  batch = d_in[2];
    const float* W1_1 = (const float*)d_in[3];
    const float* W2_1 = (const float*)d_in[4];
    const float* W1_2 = (const float*)d_in[5];
    const float* W2_2 = (const float*)d_in[6];
    const float* W1_3 = (const float*)d_in[7];
    const float* W2_3 = (const float*)d_in[8];
    const float* cW1  = (const float*)d_in[9];
    const float* cb1  = (const float*)d_in[10];
    const float* cW2  = (const float*)d_in[11];
    const float* cb2  = (const float*)d_in[12];
    float* out = (float*)d_out;

    const int EB4 = (N_EDGES + 1023) / 1024;   // 4 edges per thread
    const int NB = (N_NODES + 255) / 256;
    const int GEMM_BLOCKS = (N_NODES + 63) / 64;
    const int GATHER_BLOCKS = (N_NODES * 32 + 255) / 256;

    // Side stream: GEMM layer 1 (depends only on x/weights) overlaps the CSR build.
    cudaStream_t sB;
    cudaStreamCreateWithFlags(&sB, cudaStreamNonBlocking);
    cudaEvent_t evFork, evGemm;
    cudaEventCreateWithFlags(&evFork, cudaEventDisableTiming);
    cudaEventCreateWithFlags(&evGemm, cudaEventDisableTiming);

    cudaEventRecord(evFork, 0);
    cudaStreamWaitEvent(sB, evFork, 0);
    gemm_cat_kernel<IN_DIM, false><<<GEMM_BLOCKS, 128, 0, sB>>>(x, W1_1, W2_1);
    cudaEventRecord(evGemm, sB);

    // CSR build on the main stream (concurrent with GEMM L1)
    zero_detect_kernel<<<NB, 256>>>(ei);
    hist_kernel<<<EB4, 256>>>(ei);
    scan_block_kernel<<<N_SCAN_BLOCKS, SCAN_BLK>>>();
    scan_fin_kernel<<<N_SCAN_BLOCKS, SCAN_BLK>>>(batch);
    fill_kernel<<<EB4, 256>>>(ei);

    // Join: gather L1 needs both CSR and GEMM L1
    cudaStreamWaitEvent(0, evGemm, 0);
    gather_relu_kernel<<<GATHER_BLOCKS, 256>>>();
    // Layer 2
    gemm_cat_kernel<HID, true><<<GEMM_BLOCKS, 128>>>(nullptr, W1_2, W2_2);
    gather_relu_kernel<<<GATHER_BLOCKS, 256>>>();
    // Layer 3
    gemm_cat_kernel<HID, true><<<GEMM_BLOCKS, 128>>>(nullptr, W1_3, W2_3);
    gather_relu_kernel<<<GATHER_BLOCKS, 256>>>();

    // Pool + classify
    pool_classify_kernel<<<N_GRAPHS, HID>>>(cW1, cb1, cW2, cb2, out);
}